// round 5
// baseline (speedup 1.0000x reference)
#include <cuda_runtime.h>
#include <cstdint>

// Problem constants (fixed by the dataset)
#define NMAX   500000
#define EMAX   2000000
#define EMB    32
#define IN_DIM 65
#define TB     256
#define BLK_PER_SM 4

// Scratch (allocation-free rule: __device__ globals)
__device__ int g_total;
__device__ unsigned g_arrived;   // zero-init; returns to 0 after each barrier
__device__ unsigned g_gen;       // monotonically increases across replays (ok)
__device__ __align__(128) int  g_cnt[NMAX];     // indegree (excl. self-loop)
__device__ __align__(128) int  g_start[NMAX];   // CSR segment start
__device__ __align__(128) int  g_base[NMAX];    // bump cursor; after build = segment END
__device__ __align__(128) int2 g_packed[NMAX];  // {dinv bits, x}
__device__ __align__(128) int  g_elist[EMAX];   // CSR edge list (src ids)

// ---------------------------------------------------------------------------
// Software grid barrier (all blocks co-resident by construction)
// ---------------------------------------------------------------------------
__device__ __forceinline__ void gridbar(int nb) {
    __threadfence();
    __syncthreads();
    if (threadIdx.x == 0) {
        unsigned gen = atomicAdd(&g_gen, 0u);
        if (atomicAdd(&g_arrived, 1u) == (unsigned)nb - 1u) {
            g_arrived = 0u;
            __threadfence();
            atomicExch(&g_gen, gen + 1u);
        } else {
            while (atomicAdd(&g_gen, 0u) == gen) __nanosleep(32);
        }
        __threadfence();
    }
    __syncthreads();
}

// ---------------------------------------------------------------------------
// Fused persistent kernel: P0 init -> P1 degree -> P2 alloc -> P3 build
// ---------------------------------------------------------------------------
__global__ void __launch_bounds__(TB, BLK_PER_SM)
k_graph(const int* __restrict__ src, const int* __restrict__ dst,
        const int* __restrict__ x,
        const float* __restrict__ b_out, float* __restrict__ out,
        int N, int E, int G) {
    const int nb   = gridDim.x;
    const int gtid = blockIdx.x * TB + threadIdx.x;
    const int gstr = nb * TB;

    // ---- P0: zero counts, init out, reset bump allocator ----
    for (int i = gtid; i < N; i += gstr) g_cnt[i] = 0;
    float b0v = b_out[0];
    for (int i = gtid; i < G; i += gstr) out[i] = b0v;
    if (gtid == 0) g_total = 0;
    gridbar(nb);

    // ---- P1: indegree count, 8 edges per iteration ----
    const int nch = E >> 3;               // chunks of 8
    for (int c = gtid; c < nch; c += gstr) {
        const int4* p = reinterpret_cast<const int4*>(dst) + 2 * c;
        int4 a = p[0], b = p[1];
        atomicAdd(&g_cnt[a.x], 1); atomicAdd(&g_cnt[a.y], 1);
        atomicAdd(&g_cnt[a.z], 1); atomicAdd(&g_cnt[a.w], 1);
        atomicAdd(&g_cnt[b.x], 1); atomicAdd(&g_cnt[b.y], 1);
        atomicAdd(&g_cnt[b.z], 1); atomicAdd(&g_cnt[b.w], 1);
    }
    for (int e = nch * 8 + gtid; e < E; e += gstr) atomicAdd(&g_cnt[dst[e]], 1);
    gridbar(nb);

    // ---- P2: block-scan alloc over chunks of TB nodes ----
    {
        __shared__ int swarp[TB / 32];
        __shared__ int sbb;
        int lane = threadIdx.x & 31;
        int wid  = threadIdx.x >> 5;
        int nchunks = (N + TB - 1) / TB;
        for (int ch = blockIdx.x; ch < nchunks; ch += nb) {
            int i = ch * TB + threadIdx.x;
            int c = (i < N) ? g_cnt[i] : 0;
            int incl = c;
#pragma unroll
            for (int o = 1; o < 32; o <<= 1) {
                int v = __shfl_up_sync(0xffffffffu, incl, o);
                if (lane >= o) incl += v;
            }
            if (lane == 31) swarp[wid] = incl;
            __syncthreads();
            if (threadIdx.x == 0) {
                int s = 0;
#pragma unroll
                for (int w = 0; w < TB / 32; w++) { int v = swarp[w]; swarp[w] = s; s += v; }
                sbb = atomicAdd(&g_total, s);
            }
            __syncthreads();
            if (i < N) {
                int base = sbb + swarp[wid] + (incl - c);
                g_start[i] = base;
                g_base[i]  = base;
                g_packed[i] = make_int2(__float_as_int(rsqrtf(1.0f + (float)c)), x[i]);
            }
            __syncthreads();   // protect swarp before next chunk overwrites it
        }
    }
    gridbar(nb);

    // ---- P3: slot-claim + scatter, 8 edges per iteration ----
    for (int c = gtid; c < nch; c += gstr) {
        const int4* ps = reinterpret_cast<const int4*>(src) + 2 * c;
        const int4* pd = reinterpret_cast<const int4*>(dst) + 2 * c;
        int4 s0 = ps[0], s1 = ps[1];
        int4 d0 = pd[0], d1 = pd[1];
        int p;
        p = atomicAdd(&g_base[d0.x], 1); g_elist[p] = s0.x;
        p = atomicAdd(&g_base[d0.y], 1); g_elist[p] = s0.y;
        p = atomicAdd(&g_base[d0.z], 1); g_elist[p] = s0.z;
        p = atomicAdd(&g_base[d0.w], 1); g_elist[p] = s0.w;
        p = atomicAdd(&g_base[d1.x], 1); g_elist[p] = s1.x;
        p = atomicAdd(&g_base[d1.y], 1); g_elist[p] = s1.y;
        p = atomicAdd(&g_base[d1.z], 1); g_elist[p] = s1.z;
        p = atomicAdd(&g_base[d1.w], 1); g_elist[p] = s1.w;
    }
    for (int e = nch * 8 + gtid; e < E; e += gstr) {
        int p = atomicAdd(&g_base[dst[e]], 1);
        g_elist[p] = src[e];
    }
}

// ---------------------------------------------------------------------------
// K2: per node: gather in-edges, register-accumulate, tanh, dot, pool
// ---------------------------------------------------------------------------
__device__ __forceinline__ float tanha(float v) {
    float r;
    asm("tanh.approx.f32 %0, %1;" : "=f"(r) : "f"(v));
    return r;
}

#define WPITCH 33   // pad rows so random-row smem access spreads banks

__global__ void k_aggpool(const int* __restrict__ batch,
                          const float* __restrict__ W,
                          const float* __restrict__ b_conv,
                          const float* __restrict__ W_out,
                          float* __restrict__ out, int N) {
    __shared__ float sW[IN_DIM * WPITCH];
    __shared__ float sb[EMB];
    __shared__ float so[EMB];
    for (int t = threadIdx.x; t < IN_DIM * EMB; t += blockDim.x) {
        int r = t / EMB, cCol = t % EMB;
        sW[r * WPITCH + cCol] = W[t];
    }
    if (threadIdx.x < EMB) {
        sb[threadIdx.x] = b_conv[threadIdx.x];
        so[threadIdx.x] = W_out[threadIdx.x];
    }
    __syncthreads();

    int i = blockIdx.x * blockDim.x + threadIdx.x;
    if (i >= N) return;

    int2 p = g_packed[i];
    float dinv = __int_as_float(p.x);
    int   xi   = p.y;
    int   b0   = g_start[i];
    int   cnt  = g_base[i] - b0;         // build advanced base to segment END

    float acc[EMB];
    {
        const float* row = &sW[xi * WPITCH];
#pragma unroll
        for (int j = 0; j < EMB; j++) acc[j] = dinv * row[j];
    }
    for (int k = 0; k < cnt; k++) {
        int  s  = g_elist[b0 + k];
        int2 ps = g_packed[s];
        float ds = __int_as_float(ps.x);
        const float* row = &sW[ps.y * WPITCH];
#pragma unroll
        for (int j = 0; j < EMB; j++) acc[j] += ds * row[j];
    }

    float res = 0.f;
#pragma unroll
    for (int j = 0; j < EMB; j++)
        res += tanha(acc[j] * dinv + sb[j]) * so[j];

    atomicAdd(&out[batch[i]], res);
}

// ---------------------------------------------------------------------------
// Launch
// Inputs: 0:x[N] i32, 1:edge_index[2E] i32, 2:batch[N] i32,
//         3:W[65*32] f32, 4:b_conv[32] f32, 5:W_out[32] f32, 6:b_out[1] f32
// Output: out[G] f32
// ---------------------------------------------------------------------------
extern "C" void kernel_launch(void* const* d_in, const int* in_sizes, int n_in,
                              void* d_out, int out_size) {
    const int*   x     = (const int*)d_in[0];
    const int*   eidx  = (const int*)d_in[1];
    const int*   batch = (const int*)d_in[2];
    const float* W     = (const float*)d_in[3];
    const float* bconv = (const float*)d_in[4];
    const float* Wout  = (const float*)d_in[5];
    const float* bout  = (const float*)d_in[6];
    float* out = (float*)d_out;

    int N = in_sizes[0];
    int E = in_sizes[1] / 2;
    int G = out_size;

    const int* src = eidx;
    const int* dst = eidx + E;

    int dev = 0, sms = 148;
    cudaGetDevice(&dev);
    cudaDeviceGetAttribute(&sms, cudaDevAttrMultiProcessorCount, dev);

    int nbGraph = sms * BLK_PER_SM;          // co-resident persistent grid
    int nbN     = (N + TB - 1) / TB;

    k_graph  <<<nbGraph, TB>>>(src, dst, x, bout, out, N, E, G);
    k_aggpool<<<nbN, TB>>>(batch, W, bconv, Wout, out, N);
}

// round 6
// speedup vs baseline: 1.1090x; 1.1090x over previous
#include <cuda_runtime.h>
#include <cstdint>

// Problem constants (fixed by the dataset)
#define NMAX   500000
#define EMAX   2000000
#define EMB    32
#define IN_DIM 65
#define TB     256

// Scratch (allocation-free rule: __device__ globals)
__device__ int g_total;
__device__ __align__(128) int  g_cnt[NMAX];     // indegree (excl. self-loop)
__device__ __align__(128) int  g_start[NMAX];   // CSR segment start
__device__ __align__(128) int  g_base[NMAX];    // bump cursor; after build = segment END
__device__ __align__(128) int2 g_packed[NMAX];  // {dinv bits, x}
__device__ __align__(128) int2 g_elist[EMAX];   // CSR edge payload: {dinv_src bits, x_src}

// ---------------------------------------------------------------------------
// K1: zero counts, out[g] = b_out[0], reset bump allocator
// ---------------------------------------------------------------------------
__global__ void k_init(float* __restrict__ out, const float* __restrict__ b_out,
                       int N, int G) {
    int i = blockIdx.x * blockDim.x + threadIdx.x;
    if (i < N) g_cnt[i] = 0;
    if (i < G) out[i] = b_out[0];
    if (i == 0) g_total = 0;
}

// ---------------------------------------------------------------------------
// K2: indegree count (pure RED, no return). 8 edges/thread via 2x int4.
// ---------------------------------------------------------------------------
__global__ void k_deg(const int* __restrict__ dst, int E) {
    int t = blockIdx.x * blockDim.x + threadIdx.x;
    int e = t * 8;
    if (e + 7 < E) {
        const int4* p = reinterpret_cast<const int4*>(dst + e);
        int4 a = p[0], b = p[1];
        atomicAdd(&g_cnt[a.x], 1); atomicAdd(&g_cnt[a.y], 1);
        atomicAdd(&g_cnt[a.z], 1); atomicAdd(&g_cnt[a.w], 1);
        atomicAdd(&g_cnt[b.x], 1); atomicAdd(&g_cnt[b.y], 1);
        atomicAdd(&g_cnt[b.z], 1); atomicAdd(&g_cnt[b.w], 1);
    } else {
        for (int k = e; k < E; k++) atomicAdd(&g_cnt[dst[k]], 1);
    }
}

// ---------------------------------------------------------------------------
// K3: fused allocation: block scan of counts + one atomic block-base claim.
//     Also computes dinv = rsqrt(1+cnt) and packs {dinv, x}.
// ---------------------------------------------------------------------------
__global__ void k_alloc(const int* __restrict__ x, int N) {
    __shared__ int swarp[TB / 32];
    __shared__ int sbb;
    int i    = blockIdx.x * TB + threadIdx.x;
    int lane = threadIdx.x & 31;
    int wid  = threadIdx.x >> 5;

    int c = (i < N) ? g_cnt[i] : 0;
    int incl = c;
#pragma unroll
    for (int o = 1; o < 32; o <<= 1) {
        int v = __shfl_up_sync(0xffffffffu, incl, o);
        if (lane >= o) incl += v;
    }
    if (lane == 31) swarp[wid] = incl;
    __syncthreads();
    if (threadIdx.x == 0) {
        int s = 0;
#pragma unroll
        for (int w = 0; w < TB / 32; w++) { int v = swarp[w]; swarp[w] = s; s += v; }
        sbb = atomicAdd(&g_total, s);
    }
    __syncthreads();
    if (i < N) {
        int base = sbb + swarp[wid] + (incl - c);
        g_start[i] = base;
        g_base[i]  = base;
        g_packed[i] = make_int2(__float_as_int(rsqrtf(1.0f + (float)c)), x[i]);
    }
}

// ---------------------------------------------------------------------------
// K4: slot-claim + payload scatter:
//       pos = base[d]++ ; elist[pos] = packed[src]   ({dinv_s, x_s})
//     The packed gather is independent of the atomic return -> overlapped.
// ---------------------------------------------------------------------------
__global__ void k_build(const int* __restrict__ src, const int* __restrict__ dst,
                        int E) {
    int t = blockIdx.x * blockDim.x + threadIdx.x;
    int e = t * 4;
    if (e + 3 < E) {
        int4 s4 = *reinterpret_cast<const int4*>(src + e);
        int4 d4 = *reinterpret_cast<const int4*>(dst + e);
        int2 p0 = g_packed[s4.x];
        int2 p1 = g_packed[s4.y];
        int2 p2 = g_packed[s4.z];
        int2 p3 = g_packed[s4.w];
        int q0 = atomicAdd(&g_base[d4.x], 1);
        int q1 = atomicAdd(&g_base[d4.y], 1);
        int q2 = atomicAdd(&g_base[d4.z], 1);
        int q3 = atomicAdd(&g_base[d4.w], 1);
        g_elist[q0] = p0;
        g_elist[q1] = p1;
        g_elist[q2] = p2;
        g_elist[q3] = p3;
    } else {
        for (int k = e; k < E; k++) {
            int p = atomicAdd(&g_base[dst[k]], 1);
            g_elist[p] = g_packed[src[k]];
        }
    }
}

// ---------------------------------------------------------------------------
// K5: 4 lanes per node, 8 EMB-columns per lane.
//     Edge loop reads CONTIGUOUS int2 payloads (no random gather).
// ---------------------------------------------------------------------------
__device__ __forceinline__ float tanha(float v) {
    float r;
    asm("tanh.approx.f32 %0, %1;" : "=f"(r) : "f"(v));
    return r;
}

#define WPITCH 33   // pad rows so random-row smem access spreads banks

__global__ void __launch_bounds__(TB)
k_aggpool(const int* __restrict__ batch,
          const float* __restrict__ W,
          const float* __restrict__ b_conv,
          const float* __restrict__ W_out,
          float* __restrict__ out, int N) {
    __shared__ float sW[IN_DIM * WPITCH];
    __shared__ float sb[EMB];
    __shared__ float so[EMB];
    for (int t = threadIdx.x; t < IN_DIM * EMB; t += blockDim.x) {
        int r = t / EMB, cc = t % EMB;
        sW[r * WPITCH + cc] = W[t];
    }
    if (threadIdx.x < EMB) {
        sb[threadIdx.x] = b_conv[threadIdx.x];
        so[threadIdx.x] = W_out[threadIdx.x];
    }
    __syncthreads();

    int t    = blockIdx.x * TB + threadIdx.x;
    int node = t >> 2;          // 4 lanes per node
    int sub  = t & 3;           // column group: columns [8*sub, 8*sub+8)
    if (node >= N) return;

    int2 p = g_packed[node];    // 4 lanes same address -> broadcast
    float dinv = __int_as_float(p.x);
    int   xi   = p.y;
    int   b0   = g_start[node];
    int   cnt  = g_base[node] - b0;
    int   col0 = sub * 8;

    float acc[8];
    {
        const float* row = &sW[xi * WPITCH + col0];
#pragma unroll
        for (int j = 0; j < 8; j++) acc[j] = dinv * row[j];
    }

    int k = 0;
    for (; k + 1 < cnt; k += 2) {          // 2-edge unroll for MLP
        int2 e0 = g_elist[b0 + k];
        int2 e1 = g_elist[b0 + k + 1];
        float d0 = __int_as_float(e0.x);
        float d1 = __int_as_float(e1.x);
        const float* r0 = &sW[e0.y * WPITCH + col0];
        const float* r1 = &sW[e1.y * WPITCH + col0];
#pragma unroll
        for (int j = 0; j < 8; j++) acc[j] += d0 * r0[j];
#pragma unroll
        for (int j = 0; j < 8; j++) acc[j] += d1 * r1[j];
    }
    if (k < cnt) {
        int2 e0 = g_elist[b0 + k];
        float d0 = __int_as_float(e0.x);
        const float* r0 = &sW[e0.y * WPITCH + col0];
#pragma unroll
        for (int j = 0; j < 8; j++) acc[j] += d0 * r0[j];
    }

    float res = 0.f;
#pragma unroll
    for (int j = 0; j < 8; j++)
        res += tanha(acc[j] * dinv + sb[col0 + j]) * so[col0 + j];

    // reduce across the 4 lanes of this node
    res += __shfl_xor_sync(0xffffffffu, res, 1);
    res += __shfl_xor_sync(0xffffffffu, res, 2);
    if (sub == 0) atomicAdd(&out[batch[node]], res);
}

// ---------------------------------------------------------------------------
// Launch
// Inputs: 0:x[N] i32, 1:edge_index[2E] i32, 2:batch[N] i32,
//         3:W[65*32] f32, 4:b_conv[32] f32, 5:W_out[32] f32, 6:b_out[1] f32
// Output: out[G] f32
// ---------------------------------------------------------------------------
extern "C" void kernel_launch(void* const* d_in, const int* in_sizes, int n_in,
                              void* d_out, int out_size) {
    const int*   x     = (const int*)d_in[0];
    const int*   eidx  = (const int*)d_in[1];
    const int*   batch = (const int*)d_in[2];
    const float* W     = (const float*)d_in[3];
    const float* bconv = (const float*)d_in[4];
    const float* Wout  = (const float*)d_in[5];
    const float* bout  = (const float*)d_in[6];
    float* out = (float*)d_out;

    int N = in_sizes[0];
    int E = in_sizes[1] / 2;
    int G = out_size;

    const int* src = eidx;
    const int* dst = eidx + E;

    int initN = N > G ? N : G;
    int nbE8  = ((E + 7) / 8 + TB - 1) / TB;
    int nbE4  = ((E + 3) / 4 + TB - 1) / TB;
    int nbN   = (N + TB - 1) / TB;
    int nbN4  = ((size_t)N * 4 + TB - 1) / TB;

    k_init   <<<(initN + TB - 1) / TB, TB>>>(out, bout, N, G);
    k_deg    <<<nbE8, TB>>>(dst, E);
    k_alloc  <<<nbN, TB>>>(x, N);
    k_build  <<<nbE4, TB>>>(src, dst, E);
    k_aggpool<<<nbN4, TB>>>(batch, W, bconv, Wout, out, N);
}